// round 15
// baseline (speedup 1.0000x reference)
#include <cuda_runtime.h>
#include <math.h>

#define HDIM 512
#define NN2 32
#define LEN 2048
#define MM 1025

// bank-conflict padding for FFT buffers: bijective, strictly increasing
#define P(i) ((i) + ((i) >> 3))
#define FFT_BUF 1160

__device__ __forceinline__ float2 cmul(float2 w, float2 y) {
    return make_float2(w.x*y.x - w.y*y.y, w.x*y.y + w.y*y.x);
}

// Woodbury + bilinear post-factor for one m (r_ab already include dt)
__device__ __forceinline__ float2 wood(float R0, float I0, float R1, float I1,
                                       float R2, float I2, float R3, float I3,
                                       float t) {
    const float dr = 1.0f + R3, di = I3;
    const float idn = __fdividef(1.0f, dr*dr + di*di);
    const float numr = R1*R2 - I1*I2;
    const float numi = R1*I2 + I1*R2;
    const float cr = (numr*dr + numi*di) * idn;
    const float ci = (numi*dr - numr*di) * idn;
    const float kfr = R0 - cr, kfi = I0 - ci;
    return make_float2(kfr - kfi*t, kfi + kfr*t);   // * (1 + i t)
}

// Full Cauchy + Woodbury chain for ONE m, A/B/C/D factorization (t hoisted):
// per n: e = c - 4t^2, f = d*t,
//        mag = e^2 + f^2 = c^2 + (d^2 - 8c) t^2 + 16 t^4  (per-n k1,k2 precomp)
//        r = 1/mag, er = e*r, fr = f*r
//   A_k += a_k*er ; B_k += b_k*er ; C_k += a_k*fr ; D_k += b_k*fr
// then R_k = B_k + t*C_k ; I_k = t*A_k - D_k        (21 fma-ops/iter)
__device__ __forceinline__ float2 cauchy_m(
    const float4* __restrict__ s_cd,    // (c, d, k1, k2) = (c, d, d^2-8c, c^2)
    const float4* __restrict__ s_ab0,   // (a0, b0, a1, b1)
    const float4* __restrict__ s_ab1,   // (a2, b2, a3, b3)
    float t)
{
    const float t2  = t * t;
    const float T2n = -4.0f * t2;
    const float q16 = 16.0f * t2 * t2;   // 16 t^4

    float A0=0.f,B0=0.f,C0=0.f,D0=0.f;
    float A1=0.f,B1=0.f,C1=0.f,D1=0.f;
    float A2=0.f,B2=0.f,C2=0.f,D2=0.f;
    float A3=0.f,B3=0.f,C3=0.f,D3=0.f;

    #pragma unroll
    for (int n = 0; n < NN2; n++) {
        const float4 cd = s_cd[n];
        const float4 u  = s_ab0[n];
        const float4 v  = s_ab1[n];

        const float e   = cd.x + T2n;                      // c - 4t^2
        const float f   = cd.y * t;                        // d t
        const float mag = fmaf(cd.z, t2, cd.w) + q16;      // c^2 + k1 t^2 + 16 t^4
        const float r   = __fdividef(1.0f, mag);
        const float er  = e * r;
        const float fr  = f * r;

        A0 = fmaf(u.x, er, A0);  B0 = fmaf(u.y, er, B0);
        C0 = fmaf(u.x, fr, C0);  D0 = fmaf(u.y, fr, D0);
        A1 = fmaf(u.z, er, A1);  B1 = fmaf(u.w, er, B1);
        C1 = fmaf(u.z, fr, C1);  D1 = fmaf(u.w, fr, D1);
        A2 = fmaf(v.x, er, A2);  B2 = fmaf(v.y, er, B2);
        C2 = fmaf(v.x, fr, C2);  D2 = fmaf(v.y, fr, D2);
        A3 = fmaf(v.z, er, A3);  B3 = fmaf(v.w, er, B3);
        C3 = fmaf(v.z, fr, C3);  D3 = fmaf(v.w, fr, D3);
    }

    const float R0 = fmaf(t, C0, B0), I0 = fmaf(t, A0, -D0);
    const float R1 = fmaf(t, C1, B1), I1 = fmaf(t, A1, -D1);
    const float R2 = fmaf(t, C2, B2), I2 = fmaf(t, A2, -D2);
    const float R3 = fmaf(t, C3, B3), I3 = fmaf(t, A3, -D3);

    return wood(R0, I0, R1, I1, R2, I2, R3, I3, t);
}

// ---------------------------------------------------------------------------
// Fused kernel: one 256-thread block per h, 4 CTAs/SM.
// Phase A: Cauchy + Woodbury (A/B/C/D form, fully unrolled), 4 passes.
// Phase B: irfft(2048) via real-packing + 1024-pt radix-4 Stockham, padded.
// ---------------------------------------------------------------------------
__global__ void __launch_bounds__(256, 4)
fused_kernel(const float* __restrict__ log_dt,
             const float* __restrict__ log_w_real,
             const float* __restrict__ w_imag,
             const float* __restrict__ Bmat,
             const float* __restrict__ Cmat,
             const float* __restrict__ Pmat,
             float* __restrict__ out)
{
    __shared__ float4 s_cd[NN2];            // (c, d, d^2-8c, c^2)
    __shared__ float4 s_ab0[NN2];           // (a0, b0, a1, b1)
    __shared__ float4 s_ab1[NN2];           // (a2, b2, a3, b3)
    __shared__ float2 sBk[FFT_BUF];         // kfs (plain idx) in phase A; FFT buf (P idx)
    __shared__ float2 sA[FFT_BUF];          // FFT buf (P idx)
    __shared__ float2 tw4[768];             // tw4[j] = e^{+2*pi*i*j/1024}

    float2* const kfs = sBk;                // alias: kfs dead before first P-indexed write

    const int h   = blockIdx.x;
    const int tid = threadIdx.x;

    // twiddle table (3 entries per thread)
    #pragma unroll
    for (int r = 0; r < 3; r++) {
        const int j = tid + r * 256;
        float s, c; sincospif((float)j * (1.0f/512.0f), &s, &c);
        tw4[j] = make_float2(c, s);
    }

    if (tid < NN2) {
        const int n   = tid;
        const int idx = h * NN2 + n;
        const float dt = expf(log_dt[h]);
        const float wr = -expf(log_w_real[idx]) * dt;
        const float wi = w_imag[idx] * dt;
        const float c  = wr*wr + wi*wi;
        const float d  = -4.0f * wr;

        const float Br = Bmat[2*idx], Bi = Bmat[2*idx+1];
        const float Cr = Cmat[2*idx], Ci = Cmat[2*idx+1];
        const float Pr = Pmat[2*idx], Pi = Pmat[2*idx+1];
        float vr[4], vi[4];
        vr[0] = Br*Cr - Bi*Ci;  vi[0] = Br*Ci + Bi*Cr;   // B*C
        vr[1] = Br*Pr + Bi*Pi;  vi[1] = Bi*Pr - Br*Pi;   // B*conj(P)
        vr[2] = Pr*Cr - Pi*Ci;  vi[2] = Pr*Ci + Pi*Cr;   // P*C
        vr[3] = Pr*Pr + Pi*Pi;  vi[3] = 0.0f;            // |P|^2

        float a[4], b[4];
        #pragma unroll
        for (int k = 0; k < 4; k++) {
            a[k] =  4.0f * dt * vr[k];
            b[k] = -2.0f * dt * (vr[k]*wr + vi[k]*wi);
        }
        s_cd[n]  = make_float4(c, d, fmaf(d, d, -8.0f*c), c*c);
        s_ab0[n] = make_float4(a[0], b[0], a[1], b[1]);
        s_ab1[n] = make_float4(a[2], b[2], a[3], b[3]);
    }
    __syncthreads();

    // ================= Phase A: spectrum (kfs plain-indexed) =================
    #pragma unroll 1
    for (int pass = 0; pass < 4; pass++) {
        const int m = tid + 256 * pass;
        float s, c;
        sincospif((float)m * (1.0f/2048.0f), &s, &c);
        const float t = fminf(__fdividef(s, c), 1e8f);   // tan(pi m/L)
        kfs[m] = cauchy_m(s_cd, s_ab0, s_ab1, t);
    }
    // Nyquist m=1024 (t clamped -> converged asymptotic limit)
    if (tid == 0)
        kfs[1024] = cauchy_m(s_cd, s_ab0, s_ab1, 1e8f);
    __syncthreads();

    // ================= Phase B: irfft =================
    // Z'[m] = (E[m] + i*O[m]) / 1024  (real-packing); write P-indexed into sA
    #pragma unroll
    for (int r = 0; r < 4; r++) {
        const int m = tid + r * 256;
        float2 km = kfs[m];
        float2 kn = kfs[1024 - m];
        if (m == 0) { km.y = 0.f; kn.y = 0.f; }
        const float Ex = 0.5f * (km.x + kn.x);
        const float Ey = 0.5f * (km.y - kn.y);
        const float Ox = 0.5f * (km.x - kn.x);
        const float Oy = 0.5f * (km.y + kn.y);
        float s, c;
        sincospif((float)m * (1.0f / 1024.0f), &s, &c);
        const float Orx = Ox * c - Oy * s;
        const float Ory = Ox * s + Oy * c;
        const float scale = 1.0f / 1024.0f;
        sA[P(m)] = make_float2((Ex - Ory) * scale, (Ey + Orx) * scale);
    }

    // 5 radix-4 Stockham stages (self-sorting), inverse sign (+), P-indexed.
    float2* src = sA;
    float2* dst = sBk;
    int s_ = 1, ls = 0;
    #pragma unroll 1
    for (int ncur = 1024; ncur >= 4; ncur >>= 2) {
        __syncthreads();
        const int mq = ncur >> 2;
        const int q  = tid & (s_ - 1);
        const int p  = tid >> ls;
        const int rb = q + s_ * p;
        const float2 x0 = src[P(rb)];
        const float2 x1 = src[P(rb + s_ * mq)];
        const float2 x2 = src[P(rb + s_ * 2 * mq)];
        const float2 x3 = src[P(rb + s_ * 3 * mq)];

        const float2 va = make_float2(x0.x + x2.x, x0.y + x2.y);
        const float2 vb = make_float2(x0.x - x2.x, x0.y - x2.y);
        const float2 vc = make_float2(x1.x + x3.x, x1.y + x3.y);
        const float2 vd = make_float2(x1.x - x3.x, x1.y - x3.y);

        const float2 y0 = make_float2(va.x + vc.x, va.y + vc.y);
        const float2 y1 = make_float2(vb.x - vd.y, vb.y + vd.x);   // b + i d
        const float2 y2 = make_float2(va.x - vc.x, va.y - vc.y);
        const float2 y3 = make_float2(vb.x + vd.y, vb.y - vd.x);   // b - i d

        const float2 w1 = tw4[(p)     << ls];
        const float2 w2 = tw4[(2 * p) << ls];
        const float2 w3 = tw4[(3 * p) << ls];

        const int wb = q + s_ * 4 * p;
        dst[P(wb)]          = y0;
        dst[P(wb + s_)]     = cmul(w1, y1);
        dst[P(wb + 2 * s_)] = cmul(w2, y2);
        dst[P(wb + 3 * s_)] = cmul(w3, y3);

        float2* t = src; src = dst; dst = t;
        s_ <<= 2; ls += 2;
    }
    __syncthreads();

    // result in src (= sBk after 5 swaps); z[j] = x[2j] + i*x[2j+1]
    float4* o4 = (float4*)(out + (size_t)h * LEN);
    #pragma unroll
    for (int r = 0; r < 2; r++) {
        const int j = tid + r * 256;
        const float2 z0 = src[P(2 * j)];
        const float2 z1 = src[P(2 * j + 1)];
        o4[j] = make_float4(z0.x, z0.y, z1.x, z1.y);
    }
}

extern "C" void kernel_launch(void* const* d_in, const int* in_sizes, int n_in,
                              void* d_out, int out_size)
{
    const float* log_dt     = (const float*)d_in[0];
    const float* log_w_real = (const float*)d_in[1];
    const float* w_imag     = (const float*)d_in[2];
    const float* Bmat       = (const float*)d_in[3];
    const float* Cmat       = (const float*)d_in[4];
    const float* Pmat       = (const float*)d_in[5];
    float* out = (float*)d_out;

    fused_kernel<<<HDIM, 256>>>(log_dt, log_w_real, w_imag, Bmat, Cmat, Pmat, out);
}

// round 17
// speedup vs baseline: 4.3989x; 4.3989x over previous
#include <cuda_runtime.h>
#include <math.h>

#define HDIM 512
#define NN2 32
#define LEN 2048
#define MM 1025
#define KF_STRIDE 1028

#define N_CAUCHY_ITEMS (HDIM * 4)          // (h, quarter)
#define N_ITEMS (N_CAUCHY_ITEMS + HDIM)    // + irfft per h
#define GRID_PERSIST 592                   // 4 CTAs/SM x 148 SMs

// bank-conflict padding for FFT buffers: bijective, strictly increasing
#define P(i) ((i) + ((i) >> 3))
#define FFT_BUF 1160

__device__ float2 g_kf[HDIM * KF_STRIDE];
__device__ unsigned int g_work;
__device__ unsigned int g_done[HDIM];

__device__ __forceinline__ float2 cmul(float2 w, float2 y) {
    return make_float2(w.x*y.x - w.y*y.y, w.x*y.y + w.y*y.x);
}

// Woodbury + bilinear post-factor for one m (r_ab already include dt)
__device__ __forceinline__ float2 wood(float R0, float I0, float R1, float I1,
                                       float R2, float I2, float R3, float I3,
                                       float t) {
    const float dr = 1.0f + R3, di = I3;
    const float idn = __fdividef(1.0f, dr*dr + di*di);
    const float numr = R1*R2 - I1*I2;
    const float numi = R1*I2 + I1*R2;
    const float cr = (numr*dr + numi*di) * idn;
    const float ci = (numi*dr - numr*di) * idn;
    const float kfr = R0 - cr, kfi = I0 - ci;
    return make_float2(kfr - kfi*t, kfi + kfr*t);   // * (1 + i t)
}

// Full Cauchy + Woodbury chain for ONE m, A/B/C/D factorization (t hoisted).
// R14-proven form: e = c - 4t^2, f = d*t, mag = e^2 + f^2 (numerically safe).
__device__ __forceinline__ float2 cauchy_m(
    const float2* __restrict__ s_cd,    // (c, d)
    const float4* __restrict__ s_ab0,   // (a0, b0, a1, b1)
    const float4* __restrict__ s_ab1,   // (a2, b2, a3, b3)
    float t)
{
    const float T2n = -4.0f * t * t;

    float A0=0.f,B0=0.f,C0=0.f,D0=0.f;
    float A1=0.f,B1=0.f,C1=0.f,D1=0.f;
    float A2=0.f,B2=0.f,C2=0.f,D2=0.f;
    float A3=0.f,B3=0.f,C3=0.f,D3=0.f;

    #pragma unroll 4
    for (int n = 0; n < NN2; n++) {
        const float2 cd = s_cd[n];
        const float4 u  = s_ab0[n];
        const float4 v  = s_ab1[n];

        const float e   = cd.x + T2n;
        const float f   = cd.y * t;
        const float r   = __fdividef(1.0f, fmaf(e, e, f * f));
        const float er  = e * r;
        const float fr  = f * r;

        A0 = fmaf(u.x, er, A0);  B0 = fmaf(u.y, er, B0);
        C0 = fmaf(u.x, fr, C0);  D0 = fmaf(u.y, fr, D0);
        A1 = fmaf(u.z, er, A1);  B1 = fmaf(u.w, er, B1);
        C1 = fmaf(u.z, fr, C1);  D1 = fmaf(u.w, fr, D1);
        A2 = fmaf(v.x, er, A2);  B2 = fmaf(v.y, er, B2);
        C2 = fmaf(v.x, fr, C2);  D2 = fmaf(v.y, fr, D2);
        A3 = fmaf(v.z, er, A3);  B3 = fmaf(v.w, er, B3);
        C3 = fmaf(v.z, fr, C3);  D3 = fmaf(v.w, fr, D3);
    }

    const float R0 = fmaf(t, C0, B0), I0 = fmaf(t, A0, -D0);
    const float R1 = fmaf(t, C1, B1), I1 = fmaf(t, A1, -D1);
    const float R2 = fmaf(t, C2, B2), I2 = fmaf(t, A2, -D2);
    const float R3 = fmaf(t, C3, B3), I3 = fmaf(t, A3, -D3);

    return wood(R0, I0, R1, I1, R2, I2, R3, I3, t);
}

// ---------------------------------------------------------------------------
// Reset kernel: zero the work counter + per-h done counters (each launch).
// ---------------------------------------------------------------------------
__global__ void reset_kernel()
{
    const int tid = blockIdx.x * blockDim.x + threadIdx.x;
    if (tid < HDIM) g_done[tid] = 0u;
    if (tid == 0)   g_work = 0u;
}

// ---------------------------------------------------------------------------
// Persistent work-queue kernel: 592 CTAs pull items from g_work.
//   item < 2048 : cauchy quarter (h = item>>2, q = item&3), 256 m per item
//   item >= 2048: irfft(h = item-2048), gated on g_done[h] == 4
// Monotonic counter => all cauchy items claimed before any irfft item
// => spins always terminate (claimed cauchy items are actively executing).
// ---------------------------------------------------------------------------
__global__ void __launch_bounds__(256, 4)
persist_kernel(const float* __restrict__ log_dt,
               const float* __restrict__ log_w_real,
               const float* __restrict__ w_imag,
               const float* __restrict__ Bmat,
               const float* __restrict__ Cmat,
               const float* __restrict__ Pmat,
               float* __restrict__ out)
{
    __shared__ unsigned int s_item;
    __shared__ float2 s_cd[NN2];            // (c, d)
    __shared__ float4 s_ab0[NN2];           // (a0, b0, a1, b1)
    __shared__ float4 s_ab1[NN2];           // (a2, b2, a3, b3)
    __shared__ float2 sA[FFT_BUF];
    __shared__ float2 sB[FFT_BUF];
    __shared__ float2 tw4[768];             // tw4[j] = e^{+2*pi*i*j/1024}

    const int tid = threadIdx.x;

    // twiddle table once per CTA (used by irfft items)
    #pragma unroll
    for (int r = 0; r < 3; r++) {
        const int j = tid + r * 256;
        float s, c; sincospif((float)j * (1.0f/512.0f), &s, &c);
        tw4[j] = make_float2(c, s);
    }

    while (true) {
        __syncthreads();                    // protect s_item / smem reuse
        if (tid == 0) s_item = atomicAdd(&g_work, 1u);
        __syncthreads();
        const unsigned int item = s_item;
        if (item >= N_ITEMS) break;

        if (item < N_CAUCHY_ITEMS) {
            // ================= cauchy quarter =================
            const int h = (int)(item >> 2);
            const int q = (int)(item & 3u);

            if (tid < NN2) {
                const int n   = tid;
                const int idx = h * NN2 + n;
                const float dt = expf(log_dt[h]);
                const float wr = -expf(log_w_real[idx]) * dt;
                const float wi = w_imag[idx] * dt;

                const float Br = Bmat[2*idx], Bi = Bmat[2*idx+1];
                const float Cr = Cmat[2*idx], Ci = Cmat[2*idx+1];
                const float Pr = Pmat[2*idx], Pi = Pmat[2*idx+1];
                float vr[4], vi[4];
                vr[0] = Br*Cr - Bi*Ci;  vi[0] = Br*Ci + Bi*Cr;   // B*C
                vr[1] = Br*Pr + Bi*Pi;  vi[1] = Bi*Pr - Br*Pi;   // B*conj(P)
                vr[2] = Pr*Cr - Pi*Ci;  vi[2] = Pr*Ci + Pi*Cr;   // P*C
                vr[3] = Pr*Pr + Pi*Pi;  vi[3] = 0.0f;            // |P|^2

                float a[4], b[4];
                #pragma unroll
                for (int k = 0; k < 4; k++) {
                    a[k] =  4.0f * dt * vr[k];
                    b[k] = -2.0f * dt * (vr[k]*wr + vi[k]*wi);
                }
                s_cd[n]  = make_float2(wr*wr + wi*wi, -4.0f * wr);
                s_ab0[n] = make_float4(a[0], b[0], a[1], b[1]);
                s_ab1[n] = make_float4(a[2], b[2], a[3], b[3]);
            }
            __syncthreads();

            const int m = tid + 256 * q;
            float s, c;
            sincospif((float)m * (1.0f/2048.0f), &s, &c);
            const float t = fminf(__fdividef(s, c), 1e8f);   // tan(pi m/L)
            g_kf[h * KF_STRIDE + m] = cauchy_m(s_cd, s_ab0, s_ab1, t);

            // Nyquist m=1024 (clamped t -> converged asymptotic limit)
            if (q == 0 && tid < 32) {
                const float2 ny = cauchy_m(s_cd, s_ab0, s_ab1, 1e8f);
                if (tid == 0) g_kf[h * KF_STRIDE + 1024] = ny;
            }

            __threadfence();                // each thread: stores visible
            __syncthreads();                // all fences done
            if (tid == 0) atomicAdd(&g_done[h], 1u);   // release
        } else {
            // ================= irfft =================
            const int h = (int)(item - N_CAUCHY_ITEMS);

            if (tid == 0) {
                while (atomicAdd(&g_done[h], 0u) < 4u) { __nanosleep(64); }
            }
            __syncthreads();                // acquire ordering for whole CTA

            const float2* K = &g_kf[h * KF_STRIDE];

            // Z'[m] = (E[m] + i*O[m]) / 1024 (real-packing), P-indexed into sA
            #pragma unroll
            for (int r = 0; r < 4; r++) {
                const int m = tid + r * 256;
                float2 km = __ldcg(&K[m]);
                float2 kn = __ldcg(&K[1024 - m]);
                if (m == 0) { km.y = 0.f; kn.y = 0.f; }
                const float Ex = 0.5f * (km.x + kn.x);
                const float Ey = 0.5f * (km.y - kn.y);
                const float Ox = 0.5f * (km.x - kn.x);
                const float Oy = 0.5f * (km.y + kn.y);
                float s, c;
                sincospif((float)m * (1.0f / 1024.0f), &s, &c);
                const float Orx = Ox * c - Oy * s;
                const float Ory = Ox * s + Oy * c;
                const float scale = 1.0f / 1024.0f;
                sA[P(m)] = make_float2((Ex - Ory) * scale, (Ey + Orx) * scale);
            }

            // 5 radix-4 Stockham stages (inverse sign +), P-indexed
            float2* src = sA;
            float2* dst = sB;
            int s_ = 1, ls = 0;
            #pragma unroll 1
            for (int ncur = 1024; ncur >= 4; ncur >>= 2) {
                __syncthreads();
                const int mq = ncur >> 2;
                const int qq = tid & (s_ - 1);
                const int p  = tid >> ls;
                const int rb = qq + s_ * p;
                const float2 x0 = src[P(rb)];
                const float2 x1 = src[P(rb + s_ * mq)];
                const float2 x2 = src[P(rb + s_ * 2 * mq)];
                const float2 x3 = src[P(rb + s_ * 3 * mq)];

                const float2 va = make_float2(x0.x + x2.x, x0.y + x2.y);
                const float2 vb = make_float2(x0.x - x2.x, x0.y - x2.y);
                const float2 vc = make_float2(x1.x + x3.x, x1.y + x3.y);
                const float2 vd = make_float2(x1.x - x3.x, x1.y - x3.y);

                const float2 y0 = make_float2(va.x + vc.x, va.y + vc.y);
                const float2 y1 = make_float2(vb.x - vd.y, vb.y + vd.x);
                const float2 y2 = make_float2(va.x - vc.x, va.y - vc.y);
                const float2 y3 = make_float2(vb.x + vd.y, vb.y - vd.x);

                const float2 w1 = tw4[(p)     << ls];
                const float2 w2 = tw4[(2 * p) << ls];
                const float2 w3 = tw4[(3 * p) << ls];

                const int wb = qq + s_ * 4 * p;
                dst[P(wb)]          = y0;
                dst[P(wb + s_)]     = cmul(w1, y1);
                dst[P(wb + 2 * s_)] = cmul(w2, y2);
                dst[P(wb + 3 * s_)] = cmul(w3, y3);

                float2* t = src; src = dst; dst = t;
                s_ <<= 2; ls += 2;
            }
            __syncthreads();

            // z[j] = x[2j] + i*x[2j+1]
            float4* o4 = (float4*)(out + (size_t)h * LEN);
            #pragma unroll
            for (int r = 0; r < 2; r++) {
                const int j = tid + r * 256;
                const float2 z0 = src[P(2 * j)];
                const float2 z1 = src[P(2 * j + 1)];
                o4[j] = make_float4(z0.x, z0.y, z1.x, z1.y);
            }
        }
    }
}

extern "C" void kernel_launch(void* const* d_in, const int* in_sizes, int n_in,
                              void* d_out, int out_size)
{
    const float* log_dt     = (const float*)d_in[0];
    const float* log_w_real = (const float*)d_in[1];
    const float* w_imag     = (const float*)d_in[2];
    const float* Bmat       = (const float*)d_in[3];
    const float* Cmat       = (const float*)d_in[4];
    const float* Pmat       = (const float*)d_in[5];
    float* out = (float*)d_out;

    reset_kernel<<<1, 512>>>();
    persist_kernel<<<GRID_PERSIST, 256>>>(log_dt, log_w_real, w_imag,
                                          Bmat, Cmat, Pmat, out);
}